// round 17
// baseline (speedup 1.0000x reference)
#include <cuda_runtime.h>
#include <cuda_bf16.h>
#include <cstdint>

#define BB   4
#define SS   2048
#define HH   1024
#define NHH  16
#define HDD  64
#define MM   (BB*SS)      // 8192
#define N3   (3*HH)       // 3072
#define KK   1024
#define STR  40           // gemm smem row stride in bf16 (80B, 16B-aligned, conflict-free)
#define ASTR 72           // attn Q/K smem stride in bf16 (144B)
#define VSTR 136          // attn V^T smem stride in bf16 (272B)

// ---------------- helpers ----------------
__device__ __forceinline__ uint32_t smem_u32(const void* p) {
    uint32_t a;
    asm("{ .reg .u64 t; cvta.to.shared.u64 t, %1; cvt.u32.u64 %0, t; }" : "=r"(a) : "l"(p));
    return a;
}
__device__ __forceinline__ void ldsm4(uint32_t* r, uint32_t addr) {
    asm volatile("ldmatrix.sync.aligned.m8n8.x4.shared.b16 {%0,%1,%2,%3}, [%4];"
        : "=r"(r[0]), "=r"(r[1]), "=r"(r[2]), "=r"(r[3]) : "r"(addr));
}
__device__ __forceinline__ void mma16816(float* c, const uint32_t* a, const uint32_t* b) {
    asm volatile("mma.sync.aligned.m16n8k16.row.col.f32.bf16.bf16.f32 "
        "{%0,%1,%2,%3}, {%4,%5,%6,%7}, {%8,%9}, {%0,%1,%2,%3};"
        : "+f"(c[0]), "+f"(c[1]), "+f"(c[2]), "+f"(c[3])
        : "r"(a[0]), "r"(a[1]), "r"(a[2]), "r"(a[3]), "r"(b[0]), "r"(b[1]));
}
#define CPA(dst, src) asm volatile("cp.async.cg.shared.global [%0], [%1], 16;" :: "r"(dst), "l"(src))
#define CPC() asm volatile("cp.async.commit_group;" ::: "memory")
#define CPW0() asm volatile("cp.async.wait_group 0;" ::: "memory")

// fast exp on the FMA pipe (no MUFU)
__device__ __forceinline__ float fexp(float x) {
    float y = x * 1.4426950408889634f;
    y = fmaxf(y, -120.0f);
    const float SH = 12582912.0f;
    float z = y + SH;
    int n = __float_as_int(z) - 0x4B400000;
    float f = y - (z - SH);
    float p = 1.3333558146e-3f;
    p = fmaf(p, f, 9.6181291076e-3f);
    p = fmaf(p, f, 5.5504108665e-2f);
    p = fmaf(p, f, 2.4022650696e-1f);
    p = fmaf(p, f, 6.9314718056e-1f);
    p = fmaf(p, f, 1.0f);
    return __int_as_float(__float_as_int(p) + (n << 23));
}
__device__ __forceinline__ void bsplit2(float x, float y, uint32_t& hi, uint32_t& lo) {
    __nv_bfloat16 hx = __float2bfloat16(x);
    __nv_bfloat16 hy = __float2bfloat16(y);
    __nv_bfloat162 H(hx, hy);
    __nv_bfloat162 L(__float2bfloat16(x - __bfloat162float(hx)),
                     __float2bfloat16(y - __bfloat162float(hy)));
    hi = *reinterpret_cast<uint32_t*>(&H);
    lo = *reinterpret_cast<uint32_t*>(&L);
}

// ---------------- scratch ----------------
__device__ __align__(128) __nv_bfloat16 g_xh[(size_t)MM * KK];
__device__ __align__(128) __nv_bfloat16 g_xl[(size_t)MM * KK];
__device__ __align__(128) __nv_bfloat16 g_wqh[(size_t)N3 * KK];
__device__ __align__(128) __nv_bfloat16 g_wql[(size_t)N3 * KK];
__device__ __align__(128) __nv_bfloat16 g_wph[(size_t)HH * KK];
__device__ __align__(128) __nv_bfloat16 g_wpl[(size_t)HH * KK];
__device__ __align__(128) __nv_bfloat16 g_ch[(size_t)MM * HH];
__device__ __align__(128) __nv_bfloat16 g_cl[(size_t)MM * HH];
__device__ __align__(128) __nv_bfloat16 g_qh[(size_t)BB * NHH * SS * HDD];  // [b,h,s,d]
__device__ __align__(128) __nv_bfloat16 g_ql[(size_t)BB * NHH * SS * HDD];
__device__ __align__(128) __nv_bfloat16 g_kh[(size_t)BB * NHH * SS * HDD];
__device__ __align__(128) __nv_bfloat16 g_kl[(size_t)BB * NHH * SS * HDD];
__device__ __align__(128) __nv_bfloat16 g_vth[(size_t)BB * NHH * HDD * SS]; // [b,h,d,s]
__device__ __align__(128) __nv_bfloat16 g_vtl[(size_t)BB * NHH * HDD * SS];
__device__ float g_v[(size_t)BB * NHH * SS * HDD];                          // [b,h,s,d] fp32

// ---------------- layernorm + split ----------------
__global__ __launch_bounds__(256) void ln_kernel(const float* __restrict__ hs,
                                                 const float* __restrict__ gamma,
                                                 const float* __restrict__ beta) {
    const int row = blockIdx.x;
    const int tid = threadIdx.x;
    const float4 v = ((const float4*)(hs + (size_t)row * HH))[tid];
    float s  = v.x + v.y + v.z + v.w;
    float s2 = v.x*v.x + v.y*v.y + v.z*v.z + v.w*v.w;
    #pragma unroll
    for (int o = 16; o > 0; o >>= 1) {
        s  += __shfl_xor_sync(0xffffffffu, s,  o);
        s2 += __shfl_xor_sync(0xffffffffu, s2, o);
    }
    __shared__ float red[2][8];
    const int wid = tid >> 5, lane = tid & 31;
    if (lane == 0) { red[0][wid] = s; red[1][wid] = s2; }
    __syncthreads();
    float mean = 0.f, msq = 0.f;
    #pragma unroll
    for (int i = 0; i < 8; i++) { mean += red[0][i]; msq += red[1][i]; }
    mean *= (1.0f / HH);
    msq  *= (1.0f / HH);
    const float rstd = rsqrtf(msq - mean * mean + 1e-5f);
    const float4 g = ((const float4*)gamma)[tid];
    const float4 b = ((const float4*)beta)[tid];
    float o[4];
    o[0] = (v.x - mean) * rstd * g.x + b.x;
    o[1] = (v.y - mean) * rstd * g.y + b.y;
    o[2] = (v.z - mean) * rstd * g.z + b.z;
    o[3] = (v.w - mean) * rstd * g.w + b.w;
    const size_t off = (size_t)row * HH + tid * 4;
    uint32_t h0, l0, h1, l1;
    bsplit2(o[0], o[1], h0, l0);
    bsplit2(o[2], o[3], h1, l1);
    *(uint32_t*)(g_xh + off)     = h0;
    *(uint32_t*)(g_xh + off + 2) = h1;
    *(uint32_t*)(g_xl + off)     = l0;
    *(uint32_t*)(g_xl + off + 2) = l1;
}

// ---------------- weight transpose + split ----------------
__global__ __launch_bounds__(256) void wsplit_kernel(const float* __restrict__ W,
                                                     __nv_bfloat16* __restrict__ Th,
                                                     __nv_bfloat16* __restrict__ Tl,
                                                     int N) {
    __shared__ float sm[32][33];
    const int n0 = blockIdx.x * 32, k0 = blockIdx.y * 32;
    const int tx = threadIdx.x & 31, ty = threadIdx.x >> 5;
    #pragma unroll
    for (int i = 0; i < 4; i++) {
        const int k = ty * 4 + i;
        sm[k][tx] = W[(size_t)(k0 + k) * N + n0 + tx];
    }
    __syncthreads();
    #pragma unroll
    for (int i = 0; i < 4; i++) {
        const int n = ty * 4 + i;
        const float v = sm[tx][n];
        const __nv_bfloat16 h = __float2bfloat16(v);
        const __nv_bfloat16 l = __float2bfloat16(v - __bfloat162float(h));
        Th[(size_t)(n0 + n) * KK + k0 + tx] = h;
        Tl[(size_t)(n0 + n) * KK + k0 + tx] = l;
    }
}

// ---------------- V transpose + split: g_v[bh][s][d] -> g_vth/g_vtl [bh][d][s] ----
__global__ __launch_bounds__(256) void vtrans_kernel() {
    __shared__ float sm[32][33];
    const int s0 = blockIdx.x * 32, d0 = blockIdx.y * 32;
    const int bh = blockIdx.z;
    const int tx = threadIdx.x & 31, ty = threadIdx.x >> 5;
    const float* src = g_v + ((size_t)bh * SS) * HDD;
    #pragma unroll
    for (int i = 0; i < 4; i++) {
        const int k = ty * 4 + i;
        sm[k][tx] = src[(size_t)(s0 + k) * HDD + d0 + tx];
    }
    __syncthreads();
    #pragma unroll
    for (int i = 0; i < 4; i++) {
        const int n = ty * 4 + i;           // d within tile
        const float v = sm[tx][n];          // s = tx
        const __nv_bfloat16 h = __float2bfloat16(v);
        const __nv_bfloat16 l = __float2bfloat16(v - __bfloat162float(h));
        const size_t off = ((size_t)bh * HDD + d0 + n) * SS + s0 + tx;
        g_vth[off] = h;
        g_vtl[off] = l;
    }
}

// ---------------- split-bf16 mma.sync GEMM, cp.async pipelined ----------------
#define MMA_SMEM (8 * 128 * STR * 2)
template<int EPI>
__global__ __launch_bounds__(256) void mma_gemm_kernel(
    const __nv_bfloat16* __restrict__ Ah, const __nv_bfloat16* __restrict__ Al,
    const __nv_bfloat16* __restrict__ Bh, const __nv_bfloat16* __restrict__ Bl,
    const float* __restrict__ bias, const float* __restrict__ resid,
    float* __restrict__ outp)
{
    extern __shared__ __nv_bfloat16 smb[];
    const int tid = threadIdx.x, wid = tid >> 5, lane = tid & 31;
    const int bm = blockIdx.y, bn = blockIdx.x;
    const int wm = wid >> 2, wn = wid & 3;
    const uint32_t sbase = smem_u32(smb);

    const __nv_bfloat16* srcs[4] = {Ah + (size_t)bm * 128 * KK, Al + (size_t)bm * 128 * KK,
                                    Bh + (size_t)bn * 128 * KK, Bl + (size_t)bn * 128 * KK};

    float c[4][4][4];
    #pragma unroll
    for (int i = 0; i < 4; i++)
        #pragma unroll
        for (int j = 0; j < 4; j++)
            #pragma unroll
            for (int q = 0; q < 4; q++) c[i][j][q] = 0.f;

    auto cpload = [&](int buf, int k0) {
        #pragma unroll
        for (int op = 0; op < 4; op++) {
            const __nv_bfloat16* s = srcs[op] + k0;
            const uint32_t dbase = sbase + (uint32_t)((buf * 4 + op) * 128 * STR) * 2;
            #pragma unroll
            for (int i = 0; i < 2; i++) {
                const int id = tid + i * 256;
                const int row = id >> 2, c16 = id & 3;
                CPA(dbase + (uint32_t)(row * STR + c16 * 8) * 2,
                    s + (size_t)row * KK + c16 * 8);
            }
        }
    };
    cpload(0, 0); CPC();

    const int a_r = lane & 15, a_c = (lane >> 4) * 8;
    const int b_r = ((lane >> 4) << 3) + (lane & 7), b_c = ((lane >> 3) & 1) * 8;

    const int NCH = KK / 32;
    for (int ch = 0; ch < NCH; ch++) {
        CPW0();
        __syncthreads();
        if (ch + 1 < NCH) { cpload((ch + 1) & 1, (ch + 1) * 32); CPC(); }
        const int buf = ch & 1;
        const uint32_t base_ah = sbase + (uint32_t)((buf * 4 + 0) * 128 * STR) * 2;
        const uint32_t base_al = sbase + (uint32_t)((buf * 4 + 1) * 128 * STR) * 2;
        const uint32_t base_bh = sbase + (uint32_t)((buf * 4 + 2) * 128 * STR) * 2;
        const uint32_t base_bl = sbase + (uint32_t)((buf * 4 + 3) * 128 * STR) * 2;
        #pragma unroll
        for (int ks = 0; ks < 2; ks++) {
            uint32_t ah[4][4], al[4][4], bh2[2][4], bl2[2][4];
            #pragma unroll
            for (int mi = 0; mi < 4; mi++)
                ldsm4(ah[mi], base_ah + (uint32_t)((wm * 64 + mi * 16 + a_r) * STR + ks * 16 + a_c) * 2);
            #pragma unroll
            for (int pj = 0; pj < 2; pj++)
                ldsm4(bh2[pj], base_bh + (uint32_t)((wn * 32 + pj * 16 + b_r) * STR + ks * 16 + b_c) * 2);
            #pragma unroll
            for (int pj = 0; pj < 2; pj++)
                ldsm4(bl2[pj], base_bl + (uint32_t)((wn * 32 + pj * 16 + b_r) * STR + ks * 16 + b_c) * 2);
            #pragma unroll
            for (int mi = 0; mi < 4; mi++)
                ldsm4(al[mi], base_al + (uint32_t)((wm * 64 + mi * 16 + a_r) * STR + ks * 16 + a_c) * 2);
            #pragma unroll
            for (int mi = 0; mi < 4; mi++)
                #pragma unroll
                for (int nj = 0; nj < 4; nj++) {
                    mma16816(c[mi][nj], ah[mi], &bh2[nj >> 1][(nj & 1) * 2]);
                    mma16816(c[mi][nj], ah[mi], &bl2[nj >> 1][(nj & 1) * 2]);
                    mma16816(c[mi][nj], al[mi], &bh2[nj >> 1][(nj & 1) * 2]);
                }
        }
        __syncthreads();
    }

    // epilogue
    #pragma unroll
    for (int mi = 0; mi < 4; mi++) {
        #pragma unroll
        for (int half = 0; half < 2; half++) {
            const int r = bm * 128 + wm * 64 + mi * 16 + (lane >> 2) + half * 8;
            #pragma unroll
            for (int nj = 0; nj < 4; nj++) {
                const int n = bn * 128 + wn * 32 + nj * 8 + (lane & 3) * 2;
                const float v0 = c[mi][nj][half * 2];
                const float v1 = c[mi][nj][half * 2 + 1];
                const float2 b2 = *(const float2*)(bias + n);
                if (EPI == 0) {
                    const int part = n >> 10, rr = n & 1023;
                    const int hh = rr >> 6, d = rr & 63;
                    const int bidx = r >> 11, srow = r & 2047;
                    const size_t off = ((size_t)((bidx * NHH + hh) * SS + srow)) * HDD + d;
                    if (part == 2) {
                        *(float2*)(g_v + off) = make_float2(v0 + b2.x, v1 + b2.y);
                    } else {
                        uint32_t hi, lo;
                        bsplit2(v0 + b2.x, v1 + b2.y, hi, lo);
                        __nv_bfloat16* dh = (part == 0) ? g_qh : g_kh;
                        __nv_bfloat16* dl = (part == 0) ? g_ql : g_kl;
                        *(uint32_t*)(dh + off) = hi;
                        *(uint32_t*)(dl + off) = lo;
                    }
                } else {
                    const float2 r2 = *(const float2*)(resid + (size_t)r * HH + n);
                    *(float2*)(outp + (size_t)r * HH + n) =
                        make_float2(v0 + b2.x + r2.x, v1 + b2.y + r2.y);
                }
            }
        }
    }
}

// ---------------- tensor-core flash attention, cp.async pipelined ----------------
#define QBYTES   (128 * ASTR * 2)                    // 18432 per operand
#define VBYTES   (64 * VSTR * 2)                     // 17408 per operand
#define KOFF     (2 * QBYTES)
#define VOFF     (KOFF + 4 * QBYTES)
#define ATTN2_SMEM (VOFF + 4 * VBYTES)               // 180224
__global__ __launch_bounds__(256) void attn_mma_kernel(const float* __restrict__ amask,
                                                       float* __restrict__ scores_out) {
    extern __shared__ __nv_bfloat16 smb[];
    const uint32_t sbase = smem_u32(smb);

    const int qt = 15 - blockIdx.x;
    const int hq = blockIdx.y;
    const int bb = blockIdx.z;
    const int tid = threadIdx.x, w = tid >> 5, lane = tid & 31;
    const int q0 = qt * 128;
    const int bh = bb * NHH + hq;

    const __nv_bfloat16* Qh_g = g_qh + (size_t)bh * SS * HDD;
    const __nv_bfloat16* Ql_g = g_ql + (size_t)bh * SS * HDD;
    const __nv_bfloat16* Kh_g = g_kh + (size_t)bh * SS * HDD;
    const __nv_bfloat16* Kl_g = g_kl + (size_t)bh * SS * HDD;
    const __nv_bfloat16* Vh_g = g_vth + (size_t)bh * HDD * SS;
    const __nv_bfloat16* Vl_g = g_vtl + (size_t)bh * HDD * SS;
    float* sc = scores_out + ((size_t)bh * SS + q0) * SS;
    const float* amk = amask + bb * SS;

    // ---- Q tile cp.async (once) ----
    #pragma unroll
    for (int op = 0; op < 2; op++) {
        const __nv_bfloat16* s = (op == 0 ? Qh_g : Ql_g) + (size_t)q0 * HDD;
        const uint32_t dbase = sbase + op * QBYTES;
        #pragma unroll
        for (int i = 0; i < 4; i++) {
            const int id = tid + i * 256;
            const int row = id >> 3, c16 = id & 7;
            CPA(dbase + (uint32_t)(row * ASTR + c16 * 8) * 2, s + (size_t)row * HDD + c16 * 8);
        }
    }
    auto loadKV = [&](int buf, int k0) {
        #pragma unroll
        for (int op = 0; op < 2; op++) {
            const __nv_bfloat16* s = (op == 0 ? Kh_g : Kl_g) + (size_t)k0 * HDD;
            const uint32_t dbase = sbase + KOFF + (buf * 2 + op) * QBYTES;
            #pragma unroll
            for (int i = 0; i < 4; i++) {
                const int id = tid + i * 256;
                const int row = id >> 3, c16 = id & 7;
                CPA(dbase + (uint32_t)(row * ASTR + c16 * 8) * 2, s + (size_t)row * HDD + c16 * 8);
            }
        }
        #pragma unroll
        for (int op = 0; op < 2; op++) {
            const __nv_bfloat16* s = (op == 0 ? Vh_g : Vl_g) + k0;
            const uint32_t dbase = sbase + VOFF + (buf * 2 + op) * VBYTES;
            #pragma unroll
            for (int i = 0; i < 4; i++) {
                const int id = tid + i * 256;
                const int row = id >> 4, c16 = id & 15;
                CPA(dbase + (uint32_t)(row * VSTR + c16 * 8) * 2, s + (size_t)row * SS + c16 * 8);
            }
        }
    };
    loadKV(0, 0); CPC();

    float ctx[8][4];
    #pragma unroll
    for (int j = 0; j < 8; j++)
        #pragma unroll
        for (int q = 0; q < 4; q++) ctx[j][q] = 0.f;
    float mrow1 = -1e30f, mrow2 = -1e30f, lsum1 = 0.f, lsum2 = 0.f;

    const int a_r = lane & 15, a_c = (lane >> 4) * 8;
    const int b_r = ((lane >> 4) << 3) + (lane & 7), b_c = ((lane >> 3) & 1) * 8;
    const int colb = (lane & 3) * 2;
    const int rt1 = w * 16 + (lane >> 2), rt2 = rt1 + 8;
    const int qg1 = q0 + rt1, qg2 = q0 + rt2;

    uint32_t Qfh[4][4], Qfl[4][4];

    for (int kt = 0; kt <= qt; kt++) {
        const int k0 = kt * 128;
        CPW0();
        __syncthreads();
        if (kt == 0) {
            #pragma unroll
            for (int kg = 0; kg < 4; kg++) {
                ldsm4(Qfh[kg], sbase + (uint32_t)((w * 16 + a_r) * ASTR + kg * 16 + a_c) * 2);
                ldsm4(Qfl[kg], sbase + QBYTES + (uint32_t)((w * 16 + a_r) * ASTR + kg * 16 + a_c) * 2);
            }
        }
        if (kt + 1 <= qt) { loadKV((kt + 1) & 1, (kt + 1) * 128); CPC(); }

        const int buf = kt & 1;
        const uint32_t khb = sbase + KOFF + (buf * 2 + 0) * QBYTES;
        const uint32_t klb = sbase + KOFF + (buf * 2 + 1) * QBYTES;
        const uint32_t vhb = sbase + VOFF + (buf * 2 + 0) * VBYTES;
        const uint32_t vlb = sbase + VOFF + (buf * 2 + 1) * VBYTES;

        // ---- S = Q K^T (3-term split) ----
        float S[16][4];
        #pragma unroll
        for (int j = 0; j < 16; j++)
            #pragma unroll
            for (int q = 0; q < 4; q++) S[j][q] = 0.f;
        #pragma unroll
        for (int kg = 0; kg < 4; kg++) {
            #pragma unroll
            for (int pj = 0; pj < 8; pj++) {
                const uint32_t off = (uint32_t)((pj * 16 + b_r) * ASTR + kg * 16 + b_c) * 2;
                uint32_t bh4[4], bl4[4];
                ldsm4(bh4, khb + off);
                ldsm4(bl4, klb + off);
                mma16816(S[2 * pj],     Qfh[kg], &bh4[0]);
                mma16816(S[2 * pj],     Qfh[kg], &bl4[0]);
                mma16816(S[2 * pj],     Qfl[kg], &bh4[0]);
                mma16816(S[2 * pj + 1], Qfh[kg], &bh4[2]);
                mma16816(S[2 * pj + 1], Qfh[kg], &bl4[2]);
                mma16816(S[2 * pj + 1], Qfl[kg], &bh4[2]);
            }
        }

        // ---- scale, causal, amask, emit raw scores ----
        const bool diag = (kt == qt);
        #pragma unroll
        for (int j = 0; j < 16; j++) {
            const int c0 = k0 + j * 8 + colb;
            const float2 am2 = *(const float2*)(amk + c0);
            const float mk0 = am2.x * -10000.f, mk1 = am2.y * -10000.f;
            float s0 = fmaf(S[j][0], 0.125f, mk0);
            float s1 = fmaf(S[j][1], 0.125f, mk1);
            float s2 = fmaf(S[j][2], 0.125f, mk0);
            float s3 = fmaf(S[j][3], 0.125f, mk1);
            if (diag) {
                if (c0     > qg1) s0 = -10000.f + mk0;
                if (c0 + 1 > qg1) s1 = -10000.f + mk1;
                if (c0     > qg2) s2 = -10000.f + mk0;
                if (c0 + 1 > qg2) s3 = -10000.f + mk1;
            }
            *(float2*)(sc + (size_t)rt1 * SS + c0) = make_float2(s0, s1);
            *(float2*)(sc + (size_t)rt2 * SS + c0) = make_float2(s2, s3);
            S[j][0] = s0; S[j][1] = s1; S[j][2] = s2; S[j][3] = s3;
        }

        // ---- online softmax ----
        float mx1 = -1e30f, mx2 = -1e30f;
        #pragma unroll
        for (int j = 0; j < 16; j++) {
            mx1 = fmaxf(mx1, fmaxf(S[j][0], S[j][1]));
            mx2 = fmaxf(mx2, fmaxf(S[j][2], S[j][3]));
        }
        mx1 = fmaxf(mx1, __shfl_xor_sync(0xffffffffu, mx1, 1));
        mx1 = fmaxf(mx1, __shfl_xor_sync(0xffffffffu, mx1, 2));
        mx2 = fmaxf(mx2, __shfl_xor_sync(0xffffffffu, mx2, 1));
        mx2 = fmaxf(mx2, __shfl_xor_sync(0xffffffffu, mx2, 2));
        const float mn1 = fmaxf(mrow1, mx1), mn2 = fmaxf(mrow2, mx2);
        const float al1 = fexp(mrow1 - mn1), al2 = fexp(mrow2 - mn2);
        float sum1 = 0.f, sum2 = 0.f;
        #pragma unroll
        for (int j = 0; j < 16; j++) {
            S[j][0] = fexp(S[j][0] - mn1);
            S[j][1] = fexp(S[j][1] - mn1);
            S[j][2] = fexp(S[j][2] - mn2);
            S[j][3] = fexp(S[j][3] - mn2);
            sum1 += S[j][0] + S[j][1];
            sum2 += S[j][2] + S[j][3];
        }
        sum1 += __shfl_xor_sync(0xffffffffu, sum1, 1);
        sum1 += __shfl_xor_sync(0xffffffffu, sum1, 2);
        sum2 += __shfl_xor_sync(0xffffffffu, sum2, 1);
        sum2 += __shfl_xor_sync(0xffffffffu, sum2, 2);
        lsum1 = lsum1 * al1 + sum1; mrow1 = mn1;
        lsum2 = lsum2 * al2 + sum2; mrow2 = mn2;
        #pragma unroll
        for (int j = 0; j < 8; j++) {
            ctx[j][0] *= al1; ctx[j][1] *= al1;
            ctx[j][2] *= al2; ctx[j][3] *= al2;
        }

        // ---- ctx += P V (P in registers, 3-term split) ----
        #pragma unroll
        for (int kg = 0; kg < 8; kg++) {
            uint32_t ah[4], alr[4];
            bsplit2(S[2 * kg][0],     S[2 * kg][1],     ah[0], alr[0]);
            bsplit2(S[2 * kg][2],     S[2 * kg][3],     ah[1], alr[1]);
            bsplit2(S[2 * kg + 1][0], S[2 * kg + 1][1], ah[2], alr[2]);
            bsplit2(S[2 * kg + 1][2], S[2 * kg + 1][3], ah[3], alr[3]);
            #pragma unroll
            for (int pj = 0; pj < 4; pj++) {
                const uint32_t off = (uint32_t)((pj * 16 + b_r) * VSTR + kg * 16 + b_c) * 2;
                uint32_t bh4[4], bl4[4];
                ldsm4(bh4, vhb + off);
                ldsm4(bl4, vlb + off);
                mma16816(ctx[2 * pj],     ah,  &bh4[0]);
                mma16816(ctx[2 * pj],     alr, &bh4[0]);
                mma16816(ctx[2 * pj],     ah,  &bl4[0]);
                mma16816(ctx[2 * pj + 1], ah,  &bh4[2]);
                mma16816(ctx[2 * pj + 1], alr, &bh4[2]);
                mma16816(ctx[2 * pj + 1], ah,  &bl4[2]);
            }
        }
        __syncthreads();
    }

    // ---- tail tiles: fully causal-masked scores fill ----
    {
        const int r = tid >> 1, ch0 = (tid & 1) * 64;
        for (int kt2 = qt + 1; kt2 < 16; kt2++) {
            const int k0 = kt2 * 128;
            #pragma unroll
            for (int i = 0; i < 16; i++) {
                const int cc = ch0 + i * 4;
                const float4 a4 = *(const float4*)(amk + k0 + cc);
                const float4 val = make_float4(-10000.f + a4.x * -10000.f,
                                               -10000.f + a4.y * -10000.f,
                                               -10000.f + a4.z * -10000.f,
                                               -10000.f + a4.w * -10000.f);
                *(float4*)(sc + (size_t)r * SS + k0 + cc) = val;
            }
        }
    }

    // ---- ctx /= lsum -> bf16 hi/lo ----
    const float inv1 = 1.0f / lsum1, inv2 = 1.0f / lsum2;
    #pragma unroll
    for (int j = 0; j < 8; j++) {
        const int d = hq * 64 + j * 8 + colb;
        const size_t o1 = ((size_t)(bb * SS) + q0 + rt1) * HH + d;
        const size_t o2 = ((size_t)(bb * SS) + q0 + rt2) * HH + d;
        uint32_t hi, lo;
        bsplit2(ctx[j][0] * inv1, ctx[j][1] * inv1, hi, lo);
        *(uint32_t*)(g_ch + o1) = hi;
        *(uint32_t*)(g_cl + o1) = lo;
        bsplit2(ctx[j][2] * inv2, ctx[j][3] * inv2, hi, lo);
        *(uint32_t*)(g_ch + o2) = hi;
        *(uint32_t*)(g_cl + o2) = lo;
    }
}

// ---------------- launch ----------------
extern "C" void kernel_launch(void* const* d_in, const int* in_sizes, int n_in,
                              void* d_out, int out_size) {
    const float* hs       = (const float*)d_in[0];
    const float* amask    = (const float*)d_in[1];
    const float* c_attn_w = (const float*)d_in[2];
    const float* c_attn_b = (const float*)d_in[3];
    const float* c_proj_w = (const float*)d_in[4];
    const float* c_proj_b = (const float*)d_in[5];
    const float* ln_g     = (const float*)d_in[6];
    const float* ln_b     = (const float*)d_in[7];
    float* out = (float*)d_out;
    float* scores = out + (size_t)MM * HH;

    __nv_bfloat16 *xh, *xl, *wqh, *wql, *wph, *wpl, *ch, *cl;
    cudaGetSymbolAddress((void**)&xh,  g_xh);
    cudaGetSymbolAddress((void**)&xl,  g_xl);
    cudaGetSymbolAddress((void**)&wqh, g_wqh);
    cudaGetSymbolAddress((void**)&wql, g_wql);
    cudaGetSymbolAddress((void**)&wph, g_wph);
    cudaGetSymbolAddress((void**)&wpl, g_wpl);
    cudaGetSymbolAddress((void**)&ch,  g_ch);
    cudaGetSymbolAddress((void**)&cl,  g_cl);

    cudaFuncSetAttribute(mma_gemm_kernel<0>, cudaFuncAttributeMaxDynamicSharedMemorySize, MMA_SMEM);
    cudaFuncSetAttribute(mma_gemm_kernel<1>, cudaFuncAttributeMaxDynamicSharedMemorySize, MMA_SMEM);
    cudaFuncSetAttribute(attn_mma_kernel, cudaFuncAttributeMaxDynamicSharedMemorySize, ATTN2_SMEM);

    ln_kernel<<<MM, 256>>>(hs, ln_g, ln_b);
    wsplit_kernel<<<dim3(N3 / 32, KK / 32), 256>>>(c_attn_w, wqh, wql, N3);
    wsplit_kernel<<<dim3(HH / 32, KK / 32), 256>>>(c_proj_w, wph, wpl, HH);
    mma_gemm_kernel<0><<<dim3(N3 / 128, MM / 128), 256, MMA_SMEM>>>(
        xh, xl, wqh, wql, c_attn_b, nullptr, nullptr);
    vtrans_kernel<<<dim3(SS / 32, HDD / 32, BB * NHH), 256>>>();
    attn_mma_kernel<<<dim3(16, NHH, BB), 256, ATTN2_SMEM>>>(amask, scores);
    mma_gemm_kernel<1><<<dim3(HH / 128, MM / 128), 256, MMA_SMEM>>>(
        ch, cl, wph, wpl, c_proj_b, hs, out);
}